// round 11
// baseline (speedup 1.0000x reference)
#include <cuda_runtime.h>
#include <cuda_bf16.h>
#include <math.h>

#define B_    32
#define S_    1024
#define IN_   1024
#define H_    1024

typedef unsigned long long ull;

// ---------------- device scratch (static, no dynamic allocation) ----------------
__device__ unsigned g_flags[4][32][64];    // one 256B line per (bg, cg)
__device__ __nv_bfloat16 g_Xhi[(size_t)B_ * S_ * IN_];   // [m][k]
__device__ __nv_bfloat16 g_Xlo[(size_t)B_ * S_ * IN_];
__device__ __nv_bfloat16 g_Whi[(size_t)IN_ * H_];        // [n][k] (W_xh transposed)
__device__ __nv_bfloat16 g_Wlo[(size_t)IN_ * H_];
__device__ __nv_bfloat16 g_Hbf[2][2][B_][H_];            // [phase][hi|lo][b][j]

// ---------------- generic helpers ----------------
__device__ __forceinline__ unsigned ld_acq(const unsigned* p) {
    unsigned v;
    asm volatile("ld.global.acquire.gpu.u32 %0, [%1];" : "=r"(v) : "l"(p));
    return v;
}
__device__ __forceinline__ void st_rel(unsigned* p, unsigned v) {
    asm volatile("st.global.release.gpu.u32 [%0], %1;" :: "l"(p), "r"(v));
}
__device__ __forceinline__ ull fma2(ull a, ull b, ull c) {
    ull d;
    asm("fma.rn.f32x2 %0, %1, %2, %3;" : "=l"(d) : "l"(a), "l"(b), "l"(c));
    return d;
}
__device__ __forceinline__ ull pack2(float x) {
    ull d;
    asm("mov.b64 %0, {%1, %1};" : "=l"(d) : "f"(x));
    return d;
}
__device__ __forceinline__ void unpack2(ull v, float& lo, float& hi) {
    asm("mov.b64 {%0, %1}, %2;" : "=f"(lo), "=f"(hi) : "l"(v));
}
__device__ __forceinline__ float tanh_fast(float x) {
    float a = x * 2.88539008177792681472f;   // 2*log2(e)
    float e;
    asm("ex2.approx.f32 %0, %1;" : "=f"(e) : "f"(a));
    float d = e + 1.0f;
    float r;
    asm("rcp.approx.f32 %0, %1;" : "=f"(r) : "f"(d));
    return fmaf(-2.0f, r, 1.0f);
}
__device__ __forceinline__ void cp_async16(void* smem_dst, const void* gsrc) {
    unsigned saddr = (unsigned)__cvta_generic_to_shared(smem_dst);
    asm volatile("cp.async.cg.shared.global [%0], [%1], 16;"
                 :: "r"(saddr), "l"(gsrc) : "memory");
}
__device__ __forceinline__ void cp_async_wait_all() {
    asm volatile("cp.async.wait_all;" ::: "memory");
}
__device__ __forceinline__ void cp_async_commit() {
    asm volatile("cp.async.commit_group;" ::: "memory");
}
__device__ __forceinline__ void cp_async_wait0() {
    asm volatile("cp.async.wait_group 0;" ::: "memory");
}

// ---------------- mma helpers (verified in R10 GEMM) ----------------
__device__ __forceinline__ void ldmx4(unsigned& r0, unsigned& r1, unsigned& r2,
                                      unsigned& r3, unsigned saddr) {
    asm volatile("ldmatrix.sync.aligned.m8n8.x4.shared.b16 {%0,%1,%2,%3}, [%4];"
                 : "=r"(r0), "=r"(r1), "=r"(r2), "=r"(r3) : "r"(saddr));
}
#define MMA_BF16(d, a, b0v, b1v)                                              \
    asm volatile(                                                             \
        "mma.sync.aligned.m16n8k16.row.col.f32.bf16.bf16.f32 "                \
        "{%0,%1,%2,%3},{%4,%5,%6,%7},{%8,%9},{%0,%1,%2,%3};"                  \
        : "+f"((d)[0]), "+f"((d)[1]), "+f"((d)[2]), "+f"((d)[3])              \
        : "r"((a)[0]), "r"((a)[1]), "r"((a)[2]), "r"((a)[3]),                 \
          "r"(b0v), "r"(b1v))

// ---------------- conversion kernels (split bf16 hi/lo) ----------------
__global__ void conv_x_kernel(const float* __restrict__ X) {
    size_t i = (size_t)blockIdx.x * blockDim.x + threadIdx.x;   // float4 index
    const float4* src = (const float4*)X;
    float4 v = src[i];
    __nv_bfloat16 hv[4], lv[4];
    float vv[4] = {v.x, v.y, v.z, v.w};
#pragma unroll
    for (int j = 0; j < 4; j++) {
        hv[j] = __float2bfloat16(vv[j]);
        lv[j] = __float2bfloat16(vv[j] - __bfloat162float(hv[j]));
    }
    *(uint2*)&g_Xhi[i * 4] = *(uint2*)hv;
    *(uint2*)&g_Xlo[i * 4] = *(uint2*)lv;
}
__global__ void conv_w_kernel(const float* __restrict__ W) {
    int idx = blockIdx.x * blockDim.x + threadIdx.x;
    int n  = idx & 1023;
    int k0 = (idx >> 10) * 4;
    __nv_bfloat16 hv[4], lv[4];
#pragma unroll
    for (int j = 0; j < 4; j++) {
        float w = W[(size_t)(k0 + j) * H_ + n];
        hv[j] = __float2bfloat16(w);
        lv[j] = __float2bfloat16(w - __bfloat162float(hv[j]));
    }
    *(uint2*)&g_Whi[(size_t)n * IN_ + k0] = *(uint2*)hv;
    *(uint2*)&g_Wlo[(size_t)n * IN_ + k0] = *(uint2*)lv;
}

// ---------------- init: zero flags ----------------
__global__ void rnn_init_kernel() {
    int idx = blockIdx.x * blockDim.x + threadIdx.x;
    int stride = gridDim.x * blockDim.x;
    unsigned* f = &g_flags[0][0][0];
    for (int i = idx; i < 4 * 32 * 64; i += stride) f[i] = 0u;
}

// ---------------- HMMA split-bf16 GEMM: Xp = X @ W_xh + b (R10, unchanged) ----------------
#define GKS       32
#define TROW      40
#define TILE_ELE  (128 * TROW)
#define BUF_ELE   (4 * TILE_ELE)
#define GEMM_SMEM (2 * BUF_ELE * 2)

extern __shared__ __nv_bfloat16 gbuf[];

__global__ void __launch_bounds__(256, 1) gemm_bf16_kernel(
    const float* __restrict__ bias, float* __restrict__ C)
{
    int tid  = threadIdx.x;
    int wid  = tid >> 5;
    int lane = tid & 31;
    int brow = blockIdx.y * 128;
    int bcol = blockIdx.x * 128;

    int wm = wid >> 2;
    int wn = wid & 3;

    int tIdx = tid >> 6;
    int frow = tid & 63;
    const __nv_bfloat16* gsrc =
        (tIdx == 0) ? g_Xhi + (size_t)brow * IN_ :
        (tIdx == 1) ? g_Xlo + (size_t)brow * IN_ :
        (tIdx == 2) ? g_Whi + (size_t)bcol * IN_ :
                      g_Wlo + (size_t)bcol * IN_;
    __nv_bfloat16* dtile0 = gbuf + tIdx * TILE_ELE;

    auto fill = [&](int s, int buf) {
        __nv_bfloat16* dt = dtile0 + buf * BUF_ELE;
#pragma unroll
        for (int c = 0; c < 8; c++) {
            int row = frow + (c >> 2) * 64;
            int q   = c & 3;
            cp_async16(dt + row * TROW + q * 8,
                       gsrc + (size_t)row * IN_ + s * GKS + q * 8);
        }
    };

    int lrA = (lane & 7) + ((lane >> 3) & 1) * 8;
    int lkA = ((lane >> 4) & 1) * 8;
    int lnB = (lane & 7) + ((lane >> 4) & 1) * 8;
    int lkB = ((lane >> 3) & 1) * 8;

    unsigned sbase = (unsigned)__cvta_generic_to_shared(gbuf);
    unsigned offAhi = 0, offAlo = TILE_ELE * 2;
    unsigned offBhi = 2 * TILE_ELE * 2, offBlo = 3 * TILE_ELE * 2;

    float acc[4][4][4];
#pragma unroll
    for (int mi = 0; mi < 4; mi++)
#pragma unroll
        for (int ni = 0; ni < 4; ni++)
#pragma unroll
            for (int e = 0; e < 4; e++) acc[mi][ni][e] = 0.0f;

    fill(0, 0);
    cp_async_commit();

    for (int s = 0; s < IN_ / GKS; s++) {
        int buf = s & 1;
        cp_async_wait0();
        __syncthreads();
        if (s < IN_ / GKS - 1) {
            fill(s + 1, buf ^ 1);
            cp_async_commit();
        }
        unsigned bb = sbase + buf * (BUF_ELE * 2);

#pragma unroll
        for (int kk = 0; kk < GKS; kk += 16) {
            unsigned ah[4][4], al[4][4];
#pragma unroll
            for (int mi = 0; mi < 4; mi++) {
                unsigned ro = (unsigned)((wm * 64 + mi * 16 + lrA) * TROW + kk + lkA) * 2;
                ldmx4(ah[mi][0], ah[mi][1], ah[mi][2], ah[mi][3], bb + offAhi + ro);
                ldmx4(al[mi][0], al[mi][1], al[mi][2], al[mi][3], bb + offAlo + ro);
            }
            unsigned bh[2][4], bl[2][4];
#pragma unroll
            for (int np = 0; np < 2; np++) {
                unsigned ro = (unsigned)((wn * 32 + np * 16 + lnB) * TROW + kk + lkB) * 2;
                ldmx4(bh[np][0], bh[np][1], bh[np][2], bh[np][3], bb + offBhi + ro);
                ldmx4(bl[np][0], bl[np][1], bl[np][2], bl[np][3], bb + offBlo + ro);
            }
#pragma unroll
            for (int mi = 0; mi < 4; mi++)
#pragma unroll
                for (int ni = 0; ni < 4; ni++) {
                    int pr = ni >> 1, wh = (ni & 1) * 2;
                    MMA_BF16(acc[mi][ni], ah[mi], bh[pr][wh], bh[pr][wh + 1]);
                    MMA_BF16(acc[mi][ni], ah[mi], bl[pr][wh], bl[pr][wh + 1]);
                    MMA_BF16(acc[mi][ni], al[mi], bh[pr][wh], bh[pr][wh + 1]);
                }
        }
    }

    int gr = lane >> 2;
    int gc = (lane & 3) * 2;
#pragma unroll
    for (int ni = 0; ni < 4; ni++) {
        int col = bcol + wn * 32 + ni * 8 + gc;
        float2 bv = *(const float2*)&bias[col];
#pragma unroll
        for (int mi = 0; mi < 4; mi++) {
            int row0 = brow + wm * 64 + mi * 16 + gr;
            float2 o0 = make_float2(acc[mi][ni][0] + bv.x, acc[mi][ni][1] + bv.y);
            float2 o1 = make_float2(acc[mi][ni][2] + bv.x, acc[mi][ni][3] + bv.y);
            *(float2*)&C[(size_t)row0 * H_ + col]       = o0;
            *(float2*)&C[(size_t)(row0 + 8) * H_ + col] = o1;
        }
    }
}

// ---------------- HMMA recurrent scan ----------------
// 64 CTAs = 2 bg (16 batches) x 32 cg (32 cols). W_hh B-fragments live in
// REGISTERS (loaded once). H published as split bf16 hi/lo planes; per step:
// stage A tiles, 8 warps = 8 k-slices of 128, 96 HMMA each, 8-way k-reduce.
#define AST       1032                       // bf16 elems per staged row (pad 8)
#define ASTB      (AST * 2)                  // 2064 bytes
#define HHI_OFF   0
#define HLO_OFF   (16 * ASTB)                // 33024
#define WHI_OFF   0                          // preload-time only
#define WLO_OFF   (32 * ASTB)                // 66048
#define RED_OFF   (64 * ASTB)                // 132096
#define RED_WST   528                        // floats per warp (16*33)
#define SCAN_SMEM (RED_OFF + 8 * RED_WST * 4)   // 148992 B

extern __shared__ char scan_smem_c[];

__global__ void __launch_bounds__(256, 1) rnn_scan_kernel(
    const float* __restrict__ Whh,
    float* __restrict__ out,
    int write_last)
{
    char* smem = scan_smem_c;
    unsigned sbase = (unsigned)__cvta_generic_to_shared(smem);
    float* red = (float*)(smem + RED_OFF);

    int tid  = threadIdx.x;
    int wid  = tid >> 5;
    int lane = tid & 31;
    int cta  = blockIdx.x;
    int bg   = cta >> 5;      // 0..1 -> batches bg*16..+15
    int cg   = cta & 31;      // cols cg*32..+31
    int b0   = bg * 16;
    int j0   = cg * 32;

    int lrA = (lane & 7) + ((lane >> 3) & 1) * 8;
    int lkA = ((lane >> 4) & 1) * 8;
    int lnB = (lane & 7) + ((lane >> 4) & 1) * 8;
    int lkB = ((lane >> 3) & 1) * 8;

    // ---- preload W_hh slice -> SMEM (split bf16) -> register B-fragments ----
    {
        int j = tid & 31;
        for (int k = tid >> 5; k < H_; k += 8) {
            float w = Whh[(size_t)k * H_ + j0 + j];
            __nv_bfloat16 h = __float2bfloat16(w);
            __nv_bfloat16 l = __float2bfloat16(w - __bfloat162float(h));
            *(__nv_bfloat16*)(smem + WHI_OFF + j * ASTB + k * 2) = h;
            *(__nv_bfloat16*)(smem + WLO_OFF + j * ASTB + k * 2) = l;
        }
    }
    __syncthreads();

    int warpk = wid * 128;            // this warp's k slice
    unsigned wbh[2][8][4], wbl[2][8][4];
#pragma unroll
    for (int pr = 0; pr < 2; pr++)
#pragma unroll
        for (int ks = 0; ks < 8; ks++) {
            unsigned ro = (unsigned)((pr * 16 + lnB) * ASTB +
                                     (warpk + ks * 16 + lkB) * 2);
            ldmx4(wbh[pr][ks][0], wbh[pr][ks][1], wbh[pr][ks][2], wbh[pr][ks][3],
                  sbase + WHI_OFF + ro);
            ldmx4(wbl[pr][ks][0], wbl[pr][ks][1], wbl[pr][ks][2], wbl[pr][ks][3],
                  sbase + WLO_OFF + ro);
        }
    __syncthreads();   // W SMEM region now reusable for H staging

    // ---- per-thread output mapping: o = 2*tid, 2*tid+1 ----
    int orow = tid >> 4;              // 0..15
    int ocol = (tid & 15) * 2;        // 0,2,..,30
    size_t out_base = ((size_t)(b0 + orow) * S_) * H_ + j0 + ocol;

    unsigned* relp = &g_flags[bg][cg][0];

    // stage chunk mapping: col fixed per thread
    int s_col = tid & 127;            // 16B chunk column (k chunk)
    int s_row0 = tid >> 7;            // rows s_row0 + 2q

    float v0, v1;
    // ---- step 0: H1 = tanh(Xp0), no matmul ----
    {
        float2 xp = __ldcg((const float2*)&out[out_base]);
        v0 = tanh_fast(xp.x);
        v1 = tanh_fast(xp.y);
        __nv_bfloat162 hp, lp;
        hp.x = __float2bfloat16(v0);
        hp.y = __float2bfloat16(v1);
        lp.x = __float2bfloat16(v0 - __bfloat162float(hp.x));
        lp.y = __float2bfloat16(v1 - __bfloat162float(hp.y));
        *(__nv_bfloat162*)&g_Hbf[1][0][b0 + orow][j0 + ocol] = hp;
        *(__nv_bfloat162*)&g_Hbf[1][1][b0 + orow][j0 + ocol] = lp;
        *(float2*)&out[out_base] = make_float2(v0, v1);
        __syncthreads();
        if (tid == 0) st_rel(relp, 1u);
        if (tid < 32) {
            while (ld_acq(&g_flags[bg][tid][0]) < 1u) { }
        }
        __syncthreads();
    }

    for (int t = 1; t < S_; t++) {
        int ph = t & 1;
        float2 xp = __ldcg((const float2*)&out[out_base + (size_t)t * H_]);

        // ---- stage H hi/lo tiles (16 x 1024 bf16 each) ----
        {
            const __nv_bfloat16* ghi = &g_Hbf[ph][0][b0][0];
            const __nv_bfloat16* glo = &g_Hbf[ph][1][b0][0];
#pragma unroll
            for (int q = 0; q < 8; q++) {
                int row = s_row0 + 2 * q;
                cp_async16(smem + HHI_OFF + row * ASTB + s_col * 16,
                           ghi + (size_t)row * H_ + s_col * 8);
                cp_async16(smem + HLO_OFF + row * ASTB + s_col * 16,
                           glo + (size_t)row * H_ + s_col * 8);
            }
            cp_async_wait_all();
        }
        __syncthreads();

        // ---- MMAs: this warp's k slice, 4 n-tiles, 3 split products ----
        float acc[4][4];
#pragma unroll
        for (int ni = 0; ni < 4; ni++)
#pragma unroll
            for (int e = 0; e < 4; e++) acc[ni][e] = 0.0f;

#pragma unroll
        for (int ks = 0; ks < 8; ks++) {
            unsigned ah[4], al[4];
            unsigned ro = (unsigned)(lrA * ASTB + (warpk + ks * 16 + lkA) * 2);
            ldmx4(ah[0], ah[1], ah[2], ah[3], sbase + HHI_OFF + ro);
            ldmx4(al[0], al[1], al[2], al[3], sbase + HLO_OFF + ro);
#pragma unroll
            for (int ni = 0; ni < 4; ni++) {
                int pr = ni >> 1, wh = (ni & 1) * 2;
                MMA_BF16(acc[ni], ah, wbh[pr][ks][wh], wbh[pr][ks][wh + 1]);
                MMA_BF16(acc[ni], ah, wbl[pr][ks][wh], wbl[pr][ks][wh + 1]);
                MMA_BF16(acc[ni], al, wbh[pr][ks][wh], wbh[pr][ks][wh + 1]);
            }
        }

        // ---- write partials: red[wid][row16 x 33 + col32] ----
        {
            int gr = lane >> 2;
            int gc = (lane & 3) * 2;
            float* rw = red + wid * RED_WST;
#pragma unroll
            for (int ni = 0; ni < 4; ni++) {
#pragma unroll
                for (int e = 0; e < 4; e++) {
                    int row = gr + (e >> 1) * 8;
                    int col = ni * 8 + gc + (e & 1);
                    rw[row * 33 + col] = acc[ni][e];
                }
            }
        }
        __syncthreads();

        // ---- combine 8 k-slices, tanh, publish ----
        {
            float s0 = 0.0f, s1 = 0.0f;
            int rbase = orow * 33 + ocol;
#pragma unroll
            for (int w = 0; w < 8; w++) {
                s0 += red[w * RED_WST + rbase];
                s1 += red[w * RED_WST + rbase + 1];
            }
            v0 = tanh_fast(s0 + xp.x);
            v1 = tanh_fast(s1 + xp.y);
            int php = (t + 1) & 1;
            __nv_bfloat162 hp, lp;
            hp.x = __float2bfloat16(v0);
            hp.y = __float2bfloat16(v1);
            lp.x = __float2bfloat16(v0 - __bfloat162float(hp.x));
            lp.y = __float2bfloat16(v1 - __bfloat162float(hp.y));
            *(__nv_bfloat162*)&g_Hbf[php][0][b0 + orow][j0 + ocol] = hp;
            *(__nv_bfloat162*)&g_Hbf[php][1][b0 + orow][j0 + ocol] = lp;
        }
        __syncthreads();
        if (tid == 0) st_rel(relp, (unsigned)(t + 1));

        // out stores after release: off the critical path
        *(float2*)&out[out_base + (size_t)t * H_] = make_float2(v0, v1);

        if (tid < 32) {
            while (ld_acq(&g_flags[bg][tid][0]) < (unsigned)(t + 1)) { }
        }
        __syncthreads();
    }

    if (write_last)
        *(float2*)&out[(size_t)B_ * S_ * H_ + (size_t)(b0 + orow) * H_ + j0 + ocol] =
            make_float2(v0, v1);
}

// ---------------- launch ----------------
extern "C" void kernel_launch(void* const* d_in, const int* in_sizes, int n_in,
                              void* d_out, int out_size) {
    const float* X    = (const float*)d_in[0];
    const float* Wxh  = (const float*)d_in[1];
    const float* Whh  = (const float*)d_in[2];
    const float* bh   = (const float*)d_in[3];
    float* out        = (float*)d_out;

    conv_x_kernel<<<32768, 256>>>(X);
    conv_w_kernel<<<1024, 256>>>(Wxh);
    rnn_init_kernel<<<64, 256>>>();

    cudaFuncSetAttribute(gemm_bf16_kernel,
                         cudaFuncAttributeMaxDynamicSharedMemorySize,
                         GEMM_SMEM);
    dim3 gg(8, 256);
    gemm_bf16_kernel<<<gg, 256, GEMM_SMEM>>>(bh, out);

    cudaFuncSetAttribute(rnn_scan_kernel,
                         cudaFuncAttributeMaxDynamicSharedMemorySize,
                         SCAN_SMEM);
    int write_last = (out_size >= B_ * S_ * H_ + B_ * H_) ? 1 : 0;
    rnn_scan_kernel<<<64, 256, SCAN_SMEM>>>(Whh, out, write_last);
}

// round 12
// speedup vs baseline: 1.6385x; 1.6385x over previous
#include <cuda_runtime.h>
#include <cuda_bf16.h>
#include <math.h>

#define B_    32
#define S_    1024
#define IN_   1024
#define H_    1024

typedef unsigned long long ull;

// ---------------- device scratch (static, no dynamic allocation) ----------------
__device__ unsigned g_flags[4][32][64];    // one 256B line per (bg, cg)
__device__ __nv_bfloat16 g_Xhi[(size_t)B_ * S_ * IN_];   // [m][k]
__device__ __nv_bfloat16 g_Xlo[(size_t)B_ * S_ * IN_];
__device__ __nv_bfloat16 g_Whi[(size_t)IN_ * H_];        // [n][k] (W_xh transposed)
__device__ __nv_bfloat16 g_Wlo[(size_t)IN_ * H_];
__device__ __nv_bfloat16 g_Hbf[2][2][B_][H_];            // [phase][hi|lo][b][j]

// ---------------- generic helpers ----------------
__device__ __forceinline__ unsigned ld_acq(const unsigned* p) {
    unsigned v;
    asm volatile("ld.global.acquire.gpu.u32 %0, [%1];" : "=r"(v) : "l"(p));
    return v;
}
__device__ __forceinline__ void st_rel(unsigned* p, unsigned v) {
    asm volatile("st.global.release.gpu.u32 [%0], %1;" :: "l"(p), "r"(v));
}
__device__ __forceinline__ float tanh_fast(float x) {
    float a = x * 2.88539008177792681472f;   // 2*log2(e)
    float e;
    asm("ex2.approx.f32 %0, %1;" : "=f"(e) : "f"(a));
    float d = e + 1.0f;
    float r;
    asm("rcp.approx.f32 %0, %1;" : "=f"(r) : "f"(d));
    return fmaf(-2.0f, r, 1.0f);
}
__device__ __forceinline__ void cp_async16(void* smem_dst, const void* gsrc) {
    unsigned saddr = (unsigned)__cvta_generic_to_shared(smem_dst);
    asm volatile("cp.async.cg.shared.global [%0], [%1], 16;"
                 :: "r"(saddr), "l"(gsrc) : "memory");
}
__device__ __forceinline__ void cp_async_wait_all() {
    asm volatile("cp.async.wait_all;" ::: "memory");
}
__device__ __forceinline__ void cp_async_commit() {
    asm volatile("cp.async.commit_group;" ::: "memory");
}
__device__ __forceinline__ void cp_async_wait0() {
    asm volatile("cp.async.wait_group 0;" ::: "memory");
}

// ---------------- mma helpers (verified in R10 GEMM) ----------------
__device__ __forceinline__ void ldmx4(unsigned& r0, unsigned& r1, unsigned& r2,
                                      unsigned& r3, unsigned saddr) {
    asm volatile("ldmatrix.sync.aligned.m8n8.x4.shared.b16 {%0,%1,%2,%3}, [%4];"
                 : "=r"(r0), "=r"(r1), "=r"(r2), "=r"(r3) : "r"(saddr));
}
#define MMA_BF16(d, a, b0v, b1v)                                              \
    asm volatile(                                                             \
        "mma.sync.aligned.m16n8k16.row.col.f32.bf16.bf16.f32 "                \
        "{%0,%1,%2,%3},{%4,%5,%6,%7},{%8,%9},{%0,%1,%2,%3};"                  \
        : "+f"((d)[0]), "+f"((d)[1]), "+f"((d)[2]), "+f"((d)[3])              \
        : "r"((a)[0]), "r"((a)[1]), "r"((a)[2]), "r"((a)[3]),                 \
          "r"(b0v), "r"(b1v))

// ---------------- conversion kernels (split bf16 hi/lo) ----------------
__global__ void conv_x_kernel(const float* __restrict__ X) {
    size_t i = (size_t)blockIdx.x * blockDim.x + threadIdx.x;   // float4 index
    const float4* src = (const float4*)X;
    float4 v = src[i];
    __nv_bfloat16 hv[4], lv[4];
    float vv[4] = {v.x, v.y, v.z, v.w};
#pragma unroll
    for (int j = 0; j < 4; j++) {
        hv[j] = __float2bfloat16(vv[j]);
        lv[j] = __float2bfloat16(vv[j] - __bfloat162float(hv[j]));
    }
    *(uint2*)&g_Xhi[i * 4] = *(uint2*)hv;
    *(uint2*)&g_Xlo[i * 4] = *(uint2*)lv;
}
__global__ void conv_w_kernel(const float* __restrict__ W) {
    int idx = blockIdx.x * blockDim.x + threadIdx.x;
    int n  = idx & 1023;
    int k0 = (idx >> 10) * 4;
    __nv_bfloat16 hv[4], lv[4];
#pragma unroll
    for (int j = 0; j < 4; j++) {
        float w = W[(size_t)(k0 + j) * H_ + n];
        hv[j] = __float2bfloat16(w);
        lv[j] = __float2bfloat16(w - __bfloat162float(hv[j]));
    }
    *(uint2*)&g_Whi[(size_t)n * IN_ + k0] = *(uint2*)hv;
    *(uint2*)&g_Wlo[(size_t)n * IN_ + k0] = *(uint2*)lv;
}

// ---------------- init: zero flags ----------------
__global__ void rnn_init_kernel() {
    int idx = blockIdx.x * blockDim.x + threadIdx.x;
    int stride = gridDim.x * blockDim.x;
    unsigned* f = &g_flags[0][0][0];
    for (int i = idx; i < 4 * 32 * 64; i += stride) f[i] = 0u;
}

// ---------------- HMMA split-bf16 GEMM: Xp = X @ W_xh + b (R10, unchanged) ----------------
#define GKS       32
#define TROW      40
#define TILE_ELE  (128 * TROW)
#define BUF_ELE   (4 * TILE_ELE)
#define GEMM_SMEM (2 * BUF_ELE * 2)

extern __shared__ __nv_bfloat16 gbuf[];

__global__ void __launch_bounds__(256, 1) gemm_bf16_kernel(
    const float* __restrict__ bias, float* __restrict__ C)
{
    int tid  = threadIdx.x;
    int wid  = tid >> 5;
    int lane = tid & 31;
    int brow = blockIdx.y * 128;
    int bcol = blockIdx.x * 128;

    int wm = wid >> 2;
    int wn = wid & 3;

    int tIdx = tid >> 6;
    int frow = tid & 63;
    const __nv_bfloat16* gsrc =
        (tIdx == 0) ? g_Xhi + (size_t)brow * IN_ :
        (tIdx == 1) ? g_Xlo + (size_t)brow * IN_ :
        (tIdx == 2) ? g_Whi + (size_t)bcol * IN_ :
                      g_Wlo + (size_t)bcol * IN_;
    __nv_bfloat16* dtile0 = gbuf + tIdx * TILE_ELE;

    auto fill = [&](int s, int buf) {
        __nv_bfloat16* dt = dtile0 + buf * BUF_ELE;
#pragma unroll
        for (int c = 0; c < 8; c++) {
            int row = frow + (c >> 2) * 64;
            int q   = c & 3;
            cp_async16(dt + row * TROW + q * 8,
                       gsrc + (size_t)row * IN_ + s * GKS + q * 8);
        }
    };

    int lrA = (lane & 7) + ((lane >> 3) & 1) * 8;
    int lkA = ((lane >> 4) & 1) * 8;
    int lnB = (lane & 7) + ((lane >> 4) & 1) * 8;
    int lkB = ((lane >> 3) & 1) * 8;

    unsigned sbase = (unsigned)__cvta_generic_to_shared(gbuf);
    unsigned offAhi = 0, offAlo = TILE_ELE * 2;
    unsigned offBhi = 2 * TILE_ELE * 2, offBlo = 3 * TILE_ELE * 2;

    float acc[4][4][4];
#pragma unroll
    for (int mi = 0; mi < 4; mi++)
#pragma unroll
        for (int ni = 0; ni < 4; ni++)
#pragma unroll
            for (int e = 0; e < 4; e++) acc[mi][ni][e] = 0.0f;

    fill(0, 0);
    cp_async_commit();

    for (int s = 0; s < IN_ / GKS; s++) {
        int buf = s & 1;
        cp_async_wait0();
        __syncthreads();
        if (s < IN_ / GKS - 1) {
            fill(s + 1, buf ^ 1);
            cp_async_commit();
        }
        unsigned bb = sbase + buf * (BUF_ELE * 2);

#pragma unroll
        for (int kk = 0; kk < GKS; kk += 16) {
            unsigned ah[4][4], al[4][4];
#pragma unroll
            for (int mi = 0; mi < 4; mi++) {
                unsigned ro = (unsigned)((wm * 64 + mi * 16 + lrA) * TROW + kk + lkA) * 2;
                ldmx4(ah[mi][0], ah[mi][1], ah[mi][2], ah[mi][3], bb + offAhi + ro);
                ldmx4(al[mi][0], al[mi][1], al[mi][2], al[mi][3], bb + offAlo + ro);
            }
            unsigned bh[2][4], bl[2][4];
#pragma unroll
            for (int np = 0; np < 2; np++) {
                unsigned ro = (unsigned)((wn * 32 + np * 16 + lnB) * TROW + kk + lkB) * 2;
                ldmx4(bh[np][0], bh[np][1], bh[np][2], bh[np][3], bb + offBhi + ro);
                ldmx4(bl[np][0], bl[np][1], bl[np][2], bl[np][3], bb + offBlo + ro);
            }
#pragma unroll
            for (int mi = 0; mi < 4; mi++)
#pragma unroll
                for (int ni = 0; ni < 4; ni++) {
                    int pr = ni >> 1, wh = (ni & 1) * 2;
                    MMA_BF16(acc[mi][ni], ah[mi], bh[pr][wh], bh[pr][wh + 1]);
                    MMA_BF16(acc[mi][ni], ah[mi], bl[pr][wh], bl[pr][wh + 1]);
                    MMA_BF16(acc[mi][ni], al[mi], bh[pr][wh], bh[pr][wh + 1]);
                }
        }
    }

    int gr = lane >> 2;
    int gc = (lane & 3) * 2;
#pragma unroll
    for (int ni = 0; ni < 4; ni++) {
        int col = bcol + wn * 32 + ni * 8 + gc;
        float2 bv = *(const float2*)&bias[col];
#pragma unroll
        for (int mi = 0; mi < 4; mi++) {
            int row0 = brow + wm * 64 + mi * 16 + gr;
            float2 o0 = make_float2(acc[mi][ni][0] + bv.x, acc[mi][ni][1] + bv.y);
            float2 o1 = make_float2(acc[mi][ni][2] + bv.x, acc[mi][ni][3] + bv.y);
            *(float2*)&C[(size_t)row0 * H_ + col]       = o0;
            *(float2*)&C[(size_t)(row0 + 8) * H_ + col] = o1;
        }
    }
}

// ---------------- HMMA recurrent scan, operand-swapped ----------------
// 128 CTAs = 4 bg (8 batches) x 32 cg (32 cols), 512 threads = 16 warps.
// D[j,b] = sum_k W[j,k] * H[b,k]: A = W (m=32 j rows, frags in REGISTERS),
// B = H (n=8 batches, staged as split-bf16 hi/lo planes, 32KB/step).
// Warp k-slice = 64; per warp/step: 4 ldmatrix + 24 HMMA; 16-way k-reduce.
#define SAST      1032                       // bf16 per row (pad 8)
#define SASTB     (SAST * 2)                 // 2064 bytes
#define WJ_HI     0                          // [32][SAST] preload (transient)
#define WJ_LO     (32 * SASTB)               // 66048
#define HB_HI     0                          // [8][SAST] staging
#define HB_LO     (8 * SASTB)                // 16512
#define SRED_OFF  (16 * SASTB)               // 33024
#define SRED_WST  288                        // floats/warp: 32 j * stride 9
#define SCAN_SMEM (64 * SASTB)               // 132096 (preload dominates)

extern __shared__ char scan_smem_c[];

__global__ void __launch_bounds__(512, 1) rnn_scan_kernel(
    const float* __restrict__ Whh,
    float* __restrict__ out,
    int write_last)
{
    char* smem = scan_smem_c;
    unsigned sbase = (unsigned)__cvta_generic_to_shared(smem);
    float* red = (float*)(smem + SRED_OFF);

    int tid  = threadIdx.x;
    int wid  = tid >> 5;
    int lane = tid & 31;
    int cta  = blockIdx.x;
    int bg   = cta >> 5;      // 0..3 -> batches bg*8..+7
    int cg   = cta & 31;      // cols cg*32..+31
    int b0   = bg * 8;
    int j0   = cg * 32;

    int lrA = (lane & 7) + ((lane >> 3) & 1) * 8;
    int lkA = ((lane >> 4) & 1) * 8;

    // ---- preload W_hh slice -> SMEM split planes [j 0..31][k 0..1023] ----
    {
        int j = tid & 31;
        for (int k = tid >> 5; k < H_; k += 16) {
            float w = Whh[(size_t)k * H_ + j0 + j];
            __nv_bfloat16 h = __float2bfloat16(w);
            __nv_bfloat16 l = __float2bfloat16(w - __bfloat162float(h));
            *(__nv_bfloat16*)(smem + WJ_HI + j * SASTB + k * 2) = h;
            *(__nv_bfloat16*)(smem + WJ_LO + j * SASTB + k * 2) = l;
        }
    }
    __syncthreads();

    // ---- load W A-fragments into registers (64 regs) ----
    int warpk = wid * 64;
    unsigned wah[2][4][4], wal[2][4][4];
#pragma unroll
    for (int mi = 0; mi < 2; mi++)
#pragma unroll
        for (int ks = 0; ks < 4; ks++) {
            unsigned ro = (unsigned)((mi * 16 + lrA) * SASTB +
                                     (warpk + ks * 16 + lkA) * 2);
            ldmx4(wah[mi][ks][0], wah[mi][ks][1], wah[mi][ks][2], wah[mi][ks][3],
                  sbase + WJ_HI + ro);
            ldmx4(wal[mi][ks][0], wal[mi][ks][1], wal[mi][ks][2], wal[mi][ks][3],
                  sbase + WJ_LO + ro);
        }
    __syncthreads();   // W SMEM region now reusable for H staging + red

    // ---- H b-frag ldmatrix lane address (mat2/3 = k+16 chunk) ----
    int hrow = lane & 7;
    int hcol = (lane >> 3) * 8;       // 0,8,16,24 -> k offsets

    // ---- consumer mapping: thread (tid<256) owns output (j=lane, b=tid>>5) ----
    int ob = tid >> 5;                // 0..7 (warps 0-7)
    int oj = lane;                    // 0..31
    size_t out_base = ((size_t)(b0 + ob) * S_) * H_ + j0 + oj;

    unsigned* relp = &g_flags[bg][cg][0];

    // staging: 4 chunks of 16B per thread (2048 total = 32KB)
    float v = 0.0f;

    // ---- step 0: H1 = tanh(Xp0), no matmul ----
    {
        if (tid < 256) {
            float xp = __ldcg(&out[out_base]);
            v = tanh_fast(xp);
            __nv_bfloat16 h = __float2bfloat16(v);
            __nv_bfloat16 l = __float2bfloat16(v - __bfloat162float(h));
            g_Hbf[1][0][b0 + ob][j0 + oj] = h;
            g_Hbf[1][1][b0 + ob][j0 + oj] = l;
            out[out_base] = v;
        }
        __syncthreads();
        if (tid == 0) st_rel(relp, 1u);
        if (tid < 32) {
            while (ld_acq(&g_flags[bg][tid][0]) < 1u) { }
        }
        __syncthreads();
    }

    for (int t = 1; t < S_; t++) {
        int ph = t & 1;
        float xp = 0.0f;
        if (tid < 256) xp = __ldcg(&out[out_base + (size_t)t * H_]);

        // ---- stage H hi/lo planes (8 x 1024 bf16 each) ----
        {
#pragma unroll
            for (int q = 0; q < 4; q++) {
                int c = tid + q * 512;          // 0..2047
                int pl = c >> 10;               // 0 hi, 1 lo
                int rem = c & 1023;
                int row = rem >> 7;             // 0..7
                int col = rem & 127;            // 16B chunk
                cp_async16(smem + (pl ? HB_LO : HB_HI) + row * SASTB + col * 16,
                           &g_Hbf[ph][pl][b0 + row][col * 8]);
            }
            cp_async_wait_all();
        }
        __syncthreads();

        // ---- H b-frags: 2 ldmx4 per plane (k-slice 64) ----
        unsigned hb[2][4], lb[2][4];
#pragma unroll
        for (int c32 = 0; c32 < 2; c32++) {
            unsigned ro = (unsigned)(hrow * SASTB + (warpk + c32 * 32 + hcol) * 2);
            ldmx4(hb[c32][0], hb[c32][1], hb[c32][2], hb[c32][3],
                  sbase + HB_HI + ro);
            ldmx4(lb[c32][0], lb[c32][1], lb[c32][2], lb[c32][3],
                  sbase + HB_LO + ro);
        }

        // ---- 24 HMMA: D[j, b] partials over this warp's k-slice ----
        float acc[2][4];
#pragma unroll
        for (int mi = 0; mi < 2; mi++)
#pragma unroll
            for (int e = 0; e < 4; e++) acc[mi][e] = 0.0f;

#pragma unroll
        for (int ks = 0; ks < 4; ks++) {
            int c32 = ks >> 1, sel = (ks & 1) * 2;
            unsigned b0h = hb[c32][sel], b1h = hb[c32][sel + 1];
            unsigned b0l = lb[c32][sel], b1l = lb[c32][sel + 1];
#pragma unroll
            for (int mi = 0; mi < 2; mi++) {
                MMA_BF16(acc[mi], wah[mi][ks], b0h, b1h);   // Whi x Hhi
                MMA_BF16(acc[mi], wah[mi][ks], b0l, b1l);   // Whi x Hlo
                MMA_BF16(acc[mi], wal[mi][ks], b0h, b1h);   // Wlo x Hhi
            }
        }

        // ---- partial store: red[wid][j*9 + b] ----
        {
            int gr = lane >> 2;
            int gc = (lane & 3) * 2;
            float* rw = red + wid * SRED_WST;
#pragma unroll
            for (int mi = 0; mi < 2; mi++)
#pragma unroll
                for (int e = 0; e < 4; e++) {
                    int j = mi * 16 + gr + (e >> 1) * 8;
                    int b = gc + (e & 1);
                    rw[j * 9 + b] = acc[mi][e];
                }
        }
        __syncthreads();

        // ---- combine 16 k-slices, tanh, publish split planes ----
        if (tid < 256) {
            float s = 0.0f;
            int rbase = oj * 9 + ob;
#pragma unroll
            for (int w = 0; w < 16; w++)
                s += red[w * SRED_WST + rbase];
            v = tanh_fast(s + xp);
            int php = (t + 1) & 1;
            __nv_bfloat16 h = __float2bfloat16(v);
            __nv_bfloat16 l = __float2bfloat16(v - __bfloat162float(h));
            g_Hbf[php][0][b0 + ob][j0 + oj] = h;
            g_Hbf[php][1][b0 + ob][j0 + oj] = l;
        }
        __syncthreads();
        if (tid == 0) st_rel(relp, (unsigned)(t + 1));

        // out store after release: off the critical path
        if (tid < 256) out[out_base + (size_t)t * H_] = v;

        if (tid < 32) {
            while (ld_acq(&g_flags[bg][tid][0]) < (unsigned)(t + 1)) { }
        }
        __syncthreads();
    }

    if (write_last && tid < 256)
        out[(size_t)B_ * S_ * H_ + (size_t)(b0 + ob) * H_ + j0 + oj] = v;
}

// ---------------- launch ----------------
extern "C" void kernel_launch(void* const* d_in, const int* in_sizes, int n_in,
                              void* d_out, int out_size) {
    const float* X    = (const float*)d_in[0];
    const float* Wxh  = (const float*)d_in[1];
    const float* Whh  = (const float*)d_in[2];
    const float* bh   = (const float*)d_in[3];
    float* out        = (float*)d_out;

    conv_x_kernel<<<32768, 256>>>(X);
    conv_w_kernel<<<1024, 256>>>(Wxh);
    rnn_init_kernel<<<64, 256>>>();

    cudaFuncSetAttribute(gemm_bf16_kernel,
                         cudaFuncAttributeMaxDynamicSharedMemorySize,
                         GEMM_SMEM);
    dim3 gg(8, 256);
    gemm_bf16_kernel<<<gg, 256, GEMM_SMEM>>>(bh, out);

    cudaFuncSetAttribute(rnn_scan_kernel,
                         cudaFuncAttributeMaxDynamicSharedMemorySize,
                         SCAN_SMEM);
    int write_last = (out_size >= B_ * S_ * H_ + B_ * H_) ? 1 : 0;
    rnn_scan_kernel<<<128, 512, SCAN_SMEM>>>(Whh, out, write_last);
}

// round 13
// speedup vs baseline: 2.1339x; 1.3023x over previous
#include <cuda_runtime.h>
#include <cuda_bf16.h>
#include <math.h>

#define B_    32
#define S_    1024
#define IN_   1024
#define H_    1024

typedef unsigned long long ull;

// ---------------- device scratch (static, no dynamic allocation) ----------------
__device__ unsigned g_flags[4][32][64];    // one 256B line per (bg, cg)
__device__ __nv_bfloat16 g_Xhi[(size_t)B_ * S_ * IN_];   // [m][k]
__device__ __nv_bfloat16 g_Xlo[(size_t)B_ * S_ * IN_];
__device__ __nv_bfloat16 g_Whi[(size_t)IN_ * H_];        // [n][k] (W_xh transposed)
__device__ __nv_bfloat16 g_Wlo[(size_t)IN_ * H_];
__device__ __nv_bfloat16 g_Hbf[2][2][B_][H_];            // [phase][hi|lo][b][j]

// ---------------- generic helpers ----------------
__device__ __forceinline__ unsigned ld_acq(const unsigned* p) {
    unsigned v;
    asm volatile("ld.global.acquire.gpu.u32 %0, [%1];" : "=r"(v) : "l"(p));
    return v;
}
__device__ __forceinline__ void st_rel(unsigned* p, unsigned v) {
    asm volatile("st.global.release.gpu.u32 [%0], %1;" :: "l"(p), "r"(v));
}
__device__ __forceinline__ float tanh_fast(float x) {
    float a = x * 2.88539008177792681472f;   // 2*log2(e)
    float e;
    asm("ex2.approx.f32 %0, %1;" : "=f"(e) : "f"(a));
    float d = e + 1.0f;
    float r;
    asm("rcp.approx.f32 %0, %1;" : "=f"(r) : "f"(d));
    return fmaf(-2.0f, r, 1.0f);
}
__device__ __forceinline__ void cp_async16(void* smem_dst, const void* gsrc) {
    unsigned saddr = (unsigned)__cvta_generic_to_shared(smem_dst);
    asm volatile("cp.async.cg.shared.global [%0], [%1], 16;"
                 :: "r"(saddr), "l"(gsrc) : "memory");
}
__device__ __forceinline__ void cp_async_wait_all() {
    asm volatile("cp.async.wait_all;" ::: "memory");
}
__device__ __forceinline__ void cp_async_commit() {
    asm volatile("cp.async.commit_group;" ::: "memory");
}
__device__ __forceinline__ void cp_async_wait0() {
    asm volatile("cp.async.wait_group 0;" ::: "memory");
}

// ---------------- mma helpers (verified in R10 GEMM) ----------------
__device__ __forceinline__ void ldmx4(unsigned& r0, unsigned& r1, unsigned& r2,
                                      unsigned& r3, unsigned saddr) {
    asm volatile("ldmatrix.sync.aligned.m8n8.x4.shared.b16 {%0,%1,%2,%3}, [%4];"
                 : "=r"(r0), "=r"(r1), "=r"(r2), "=r"(r3) : "r"(saddr));
}
#define MMA_BF16(d, a, b0v, b1v)                                              \
    asm volatile(                                                             \
        "mma.sync.aligned.m16n8k16.row.col.f32.bf16.bf16.f32 "                \
        "{%0,%1,%2,%3},{%4,%5,%6,%7},{%8,%9},{%0,%1,%2,%3};"                  \
        : "+f"((d)[0]), "+f"((d)[1]), "+f"((d)[2]), "+f"((d)[3])              \
        : "r"((a)[0]), "r"((a)[1]), "r"((a)[2]), "r"((a)[3]),                 \
          "r"(b0v), "r"(b1v))

// ---------------- conversion kernels (split bf16 hi/lo) ----------------
__global__ void conv_x_kernel(const float* __restrict__ X) {
    size_t i = (size_t)blockIdx.x * blockDim.x + threadIdx.x;   // float4 index
    const float4* src = (const float4*)X;
    float4 v = src[i];
    __nv_bfloat16 hv[4], lv[4];
    float vv[4] = {v.x, v.y, v.z, v.w};
#pragma unroll
    for (int j = 0; j < 4; j++) {
        hv[j] = __float2bfloat16(vv[j]);
        lv[j] = __float2bfloat16(vv[j] - __bfloat162float(hv[j]));
    }
    *(uint2*)&g_Xhi[i * 4] = *(uint2*)hv;
    *(uint2*)&g_Xlo[i * 4] = *(uint2*)lv;
}
__global__ void conv_w_kernel(const float* __restrict__ W) {
    int idx = blockIdx.x * blockDim.x + threadIdx.x;
    int n  = idx & 1023;
    int k0 = (idx >> 10) * 4;
    __nv_bfloat16 hv[4], lv[4];
#pragma unroll
    for (int j = 0; j < 4; j++) {
        float w = W[(size_t)(k0 + j) * H_ + n];
        hv[j] = __float2bfloat16(w);
        lv[j] = __float2bfloat16(w - __bfloat162float(hv[j]));
    }
    *(uint2*)&g_Whi[(size_t)n * IN_ + k0] = *(uint2*)hv;
    *(uint2*)&g_Wlo[(size_t)n * IN_ + k0] = *(uint2*)lv;
}

// ---------------- init: zero flags ----------------
__global__ void rnn_init_kernel() {
    int idx = blockIdx.x * blockDim.x + threadIdx.x;
    int stride = gridDim.x * blockDim.x;
    unsigned* f = &g_flags[0][0][0];
    for (int i = idx; i < 4 * 32 * 64; i += stride) f[i] = 0u;
}

// ---------------- HMMA split-bf16 GEMM: Xp = X @ W_xh + b (R10, unchanged) ----------------
#define GKS       32
#define TROW      40
#define TILE_ELE  (128 * TROW)
#define BUF_ELE   (4 * TILE_ELE)
#define GEMM_SMEM (2 * BUF_ELE * 2)

extern __shared__ __nv_bfloat16 gbuf[];

__global__ void __launch_bounds__(256, 1) gemm_bf16_kernel(
    const float* __restrict__ bias, float* __restrict__ C)
{
    int tid  = threadIdx.x;
    int wid  = tid >> 5;
    int lane = tid & 31;
    int brow = blockIdx.y * 128;
    int bcol = blockIdx.x * 128;

    int wm = wid >> 2;
    int wn = wid & 3;

    int tIdx = tid >> 6;
    int frow = tid & 63;
    const __nv_bfloat16* gsrc =
        (tIdx == 0) ? g_Xhi + (size_t)brow * IN_ :
        (tIdx == 1) ? g_Xlo + (size_t)brow * IN_ :
        (tIdx == 2) ? g_Whi + (size_t)bcol * IN_ :
                      g_Wlo + (size_t)bcol * IN_;
    __nv_bfloat16* dtile0 = gbuf + tIdx * TILE_ELE;

    auto fill = [&](int s, int buf) {
        __nv_bfloat16* dt = dtile0 + buf * BUF_ELE;
#pragma unroll
        for (int c = 0; c < 8; c++) {
            int row = frow + (c >> 2) * 64;
            int q   = c & 3;
            cp_async16(dt + row * TROW + q * 8,
                       gsrc + (size_t)row * IN_ + s * GKS + q * 8);
        }
    };

    int lrA = (lane & 7) + ((lane >> 3) & 1) * 8;
    int lkA = ((lane >> 4) & 1) * 8;
    int lnB = (lane & 7) + ((lane >> 4) & 1) * 8;
    int lkB = ((lane >> 3) & 1) * 8;

    unsigned sbase = (unsigned)__cvta_generic_to_shared(gbuf);
    unsigned offAhi = 0, offAlo = TILE_ELE * 2;
    unsigned offBhi = 2 * TILE_ELE * 2, offBlo = 3 * TILE_ELE * 2;

    float acc[4][4][4];
#pragma unroll
    for (int mi = 0; mi < 4; mi++)
#pragma unroll
        for (int ni = 0; ni < 4; ni++)
#pragma unroll
            for (int e = 0; e < 4; e++) acc[mi][ni][e] = 0.0f;

    fill(0, 0);
    cp_async_commit();

    for (int s = 0; s < IN_ / GKS; s++) {
        int buf = s & 1;
        cp_async_wait0();
        __syncthreads();
        if (s < IN_ / GKS - 1) {
            fill(s + 1, buf ^ 1);
            cp_async_commit();
        }
        unsigned bb = sbase + buf * (BUF_ELE * 2);

#pragma unroll
        for (int kk = 0; kk < GKS; kk += 16) {
            unsigned ah[4][4], al[4][4];
#pragma unroll
            for (int mi = 0; mi < 4; mi++) {
                unsigned ro = (unsigned)((wm * 64 + mi * 16 + lrA) * TROW + kk + lkA) * 2;
                ldmx4(ah[mi][0], ah[mi][1], ah[mi][2], ah[mi][3], bb + offAhi + ro);
                ldmx4(al[mi][0], al[mi][1], al[mi][2], al[mi][3], bb + offAlo + ro);
            }
            unsigned bh[2][4], bl[2][4];
#pragma unroll
            for (int np = 0; np < 2; np++) {
                unsigned ro = (unsigned)((wn * 32 + np * 16 + lnB) * TROW + kk + lkB) * 2;
                ldmx4(bh[np][0], bh[np][1], bh[np][2], bh[np][3], bb + offBhi + ro);
                ldmx4(bl[np][0], bl[np][1], bl[np][2], bl[np][3], bb + offBlo + ro);
            }
#pragma unroll
            for (int mi = 0; mi < 4; mi++)
#pragma unroll
                for (int ni = 0; ni < 4; ni++) {
                    int pr = ni >> 1, wh = (ni & 1) * 2;
                    MMA_BF16(acc[mi][ni], ah[mi], bh[pr][wh], bh[pr][wh + 1]);
                    MMA_BF16(acc[mi][ni], ah[mi], bl[pr][wh], bl[pr][wh + 1]);
                    MMA_BF16(acc[mi][ni], al[mi], bh[pr][wh], bh[pr][wh + 1]);
                }
        }
    }

    int gr = lane >> 2;
    int gc = (lane & 3) * 2;
#pragma unroll
    for (int ni = 0; ni < 4; ni++) {
        int col = bcol + wn * 32 + ni * 8 + gc;
        float2 bv = *(const float2*)&bias[col];
#pragma unroll
        for (int mi = 0; mi < 4; mi++) {
            int row0 = brow + wm * 64 + mi * 16 + gr;
            float2 o0 = make_float2(acc[mi][ni][0] + bv.x, acc[mi][ni][1] + bv.y);
            float2 o1 = make_float2(acc[mi][ni][2] + bv.x, acc[mi][ni][3] + bv.y);
            *(float2*)&C[(size_t)row0 * H_ + col]       = o0;
            *(float2*)&C[(size_t)(row0 + 8) * H_ + col] = o1;
        }
    }
}

// ---------------- HMMA recurrent scan, fine-grained dataflow ----------------
// 128 CTAs = 4 bg (8 batches) x 32 cg (32 cols), 512 threads = 16 warps.
// D[j,b] = sum_k W[j,k] * H[b,k]: A = W (frags in registers), B = H (staged).
// Warp w's k-slice [64w, 64w+64) depends on producers cg' = 2w, 2w+1 ONLY:
// each warp polls its own 2 flags, stages its own 2KB, computes immediately.
// CTA-wide syncs per step: 2 (pre-reduce, pre-release).
#define SAST      1032                       // bf16 per row (pad 8)
#define SASTB     (SAST * 2)                 // 2064 bytes
#define WJ_HI     0                          // [32][SAST] preload (transient)
#define WJ_LO     (32 * SASTB)
#define HB_HI     0                          // [8][SAST] staging
#define HB_LO     (8 * SASTB)
#define SRED_OFF  (16 * SASTB)               // 33024
#define SRED_WST  288                        // floats/warp: 32 j * stride 9
#define SCAN_SMEM (64 * SASTB)               // 132096 (preload dominates)

extern __shared__ char scan_smem_c[];

__global__ void __launch_bounds__(512, 1) rnn_scan_kernel(
    const float* __restrict__ Whh,
    float* __restrict__ out,
    int write_last)
{
    char* smem = scan_smem_c;
    unsigned sbase = (unsigned)__cvta_generic_to_shared(smem);
    float* red = (float*)(smem + SRED_OFF);

    int tid  = threadIdx.x;
    int wid  = tid >> 5;
    int lane = tid & 31;
    int cta  = blockIdx.x;
    int bg   = cta >> 5;      // 0..3 -> batches bg*8..+7
    int cg   = cta & 31;      // cols cg*32..+31
    int b0   = bg * 8;
    int j0   = cg * 32;

    int lrA = (lane & 7) + ((lane >> 3) & 1) * 8;
    int lkA = ((lane >> 4) & 1) * 8;

    // ---- preload W_hh slice -> SMEM split planes [j 0..31][k 0..1023] ----
    {
        int j = tid & 31;
        for (int k = tid >> 5; k < H_; k += 16) {
            float w = Whh[(size_t)k * H_ + j0 + j];
            __nv_bfloat16 h = __float2bfloat16(w);
            __nv_bfloat16 l = __float2bfloat16(w - __bfloat162float(h));
            *(__nv_bfloat16*)(smem + WJ_HI + j * SASTB + k * 2) = h;
            *(__nv_bfloat16*)(smem + WJ_LO + j * SASTB + k * 2) = l;
        }
    }
    __syncthreads();

    // ---- load W A-fragments into registers (64 regs) ----
    int warpk = wid * 64;
    unsigned wah[2][4][4], wal[2][4][4];
#pragma unroll
    for (int mi = 0; mi < 2; mi++)
#pragma unroll
        for (int ks = 0; ks < 4; ks++) {
            unsigned ro = (unsigned)((mi * 16 + lrA) * SASTB +
                                     (warpk + ks * 16 + lkA) * 2);
            ldmx4(wah[mi][ks][0], wah[mi][ks][1], wah[mi][ks][2], wah[mi][ks][3],
                  sbase + WJ_HI + ro);
            ldmx4(wal[mi][ks][0], wal[mi][ks][1], wal[mi][ks][2], wal[mi][ks][3],
                  sbase + WJ_LO + ro);
        }
    __syncthreads();   // W SMEM region now reusable for H staging + red

    // ---- H b-frag ldmatrix lane address ----
    int hrow = lane & 7;
    int hcol = (lane >> 3) * 8;

    // ---- consumer mapping: thread (tid<256) owns output (j=lane, b=tid>>5) ----
    int ob = tid >> 5;
    int oj = lane;
    size_t out_base = ((size_t)(b0 + ob) * S_) * H_ + j0 + oj;

    unsigned* relp = &g_flags[bg][cg][0];
    // warp w polls its 2 producers: lanes alternate the two flag lines
    const unsigned* wpoll = &g_flags[bg][2 * wid + (lane & 1)][0];

    // per-lane staging map: 4 chunks, col16 = lane&7 fixed, plane/row vary
    int s_col16 = 8 * wid + (lane & 7);      // 16B-chunk column in full row
    float v = 0.0f;

    // ---- step 0: H1 = tanh(Xp0), no matmul ----
    {
        if (tid < 256) {
            float xp = __ldcg(&out[out_base]);
            v = tanh_fast(xp);
            __nv_bfloat16 h = __float2bfloat16(v);
            __nv_bfloat16 l = __float2bfloat16(v - __bfloat162float(h));
            g_Hbf[1][0][b0 + ob][j0 + oj] = h;
            g_Hbf[1][1][b0 + ob][j0 + oj] = l;
            out[out_base] = v;
        }
        __syncthreads();
        if (tid == 0) st_rel(relp, 1u);
    }

    for (int t = 1; t < S_; t++) {
        int ph = t & 1;
        float xp = 0.0f;
        if (tid < 256) xp = __ldcg(&out[out_base + (size_t)t * H_]);

        // ---- per-warp poll of the warp's 2 producers ----
        while (ld_acq(wpoll) < (unsigned)t) { }
        __syncwarp();

        // ---- stage warp's own k-slice: 8 rows x 64 cols x 2 planes = 2KB ----
        {
#pragma unroll
            for (int q = 0; q < 4; q++) {
                int c   = lane + q * 32;        // 0..127
                int pl  = c >> 6;               // 0 hi, 1 lo
                int row = (c >> 3) & 7;         // 0..7
                cp_async16(smem + (pl ? HB_LO : HB_HI) + row * SASTB + s_col16 * 16,
                           &g_Hbf[ph][pl][b0 + row][s_col16 * 8]);
            }
            cp_async_wait_all();
            __syncwarp();
        }

        // ---- H b-frags: 2 ldmx4 per plane (k-slice 64) ----
        unsigned hb[2][4], lb[2][4];
#pragma unroll
        for (int c32 = 0; c32 < 2; c32++) {
            unsigned ro = (unsigned)(hrow * SASTB + (warpk + c32 * 32 + hcol) * 2);
            ldmx4(hb[c32][0], hb[c32][1], hb[c32][2], hb[c32][3],
                  sbase + HB_HI + ro);
            ldmx4(lb[c32][0], lb[c32][1], lb[c32][2], lb[c32][3],
                  sbase + HB_LO + ro);
        }

        // ---- 24 HMMA: D[j, b] partials over this warp's k-slice ----
        float acc[2][4];
#pragma unroll
        for (int mi = 0; mi < 2; mi++)
#pragma unroll
            for (int e = 0; e < 4; e++) acc[mi][e] = 0.0f;

#pragma unroll
        for (int ks = 0; ks < 4; ks++) {
            int c32 = ks >> 1, sel = (ks & 1) * 2;
            unsigned b0h = hb[c32][sel], b1h = hb[c32][sel + 1];
            unsigned b0l = lb[c32][sel], b1l = lb[c32][sel + 1];
#pragma unroll
            for (int mi = 0; mi < 2; mi++) {
                MMA_BF16(acc[mi], wah[mi][ks], b0h, b1h);   // Whi x Hhi
                MMA_BF16(acc[mi], wah[mi][ks], b0l, b1l);   // Whi x Hlo
                MMA_BF16(acc[mi], wal[mi][ks], b0h, b1h);   // Wlo x Hhi
            }
        }

        // ---- partial store: red[wid][j*9 + b] ----
        {
            int gr = lane >> 2;
            int gc = (lane & 3) * 2;
            float* rw = red + wid * SRED_WST;
#pragma unroll
            for (int mi = 0; mi < 2; mi++)
#pragma unroll
                for (int e = 0; e < 4; e++) {
                    int j = mi * 16 + gr + (e >> 1) * 8;
                    int b = gc + (e & 1);
                    rw[j * 9 + b] = acc[mi][e];
                }
        }
        __syncthreads();

        // ---- combine 16 k-slices, tanh, publish split planes ----
        if (tid < 256) {
            float s = 0.0f;
            int rbase = oj * 9 + ob;
#pragma unroll
            for (int w = 0; w < 16; w++)
                s += red[w * SRED_WST + rbase];
            v = tanh_fast(s + xp);
            int php = (t + 1) & 1;
            __nv_bfloat16 h = __float2bfloat16(v);
            __nv_bfloat16 l = __float2bfloat16(v - __bfloat162float(h));
            g_Hbf[php][0][b0 + ob][j0 + oj] = h;
            g_Hbf[php][1][b0 + ob][j0 + oj] = l;
        }
        __syncthreads();
        if (tid == 0) st_rel(relp, (unsigned)(t + 1));

        // out store after release: off the critical path
        if (tid < 256) out[out_base + (size_t)t * H_] = v;
    }

    if (write_last && tid < 256)
        out[(size_t)B_ * S_ * H_ + (size_t)(b0 + ob) * H_ + j0 + oj] = v;
}

// ---------------- launch ----------------
extern "C" void kernel_launch(void* const* d_in, const int* in_sizes, int n_in,
                              void* d_out, int out_size) {
    const float* X    = (const float*)d_in[0];
    const float* Wxh  = (const float*)d_in[1];
    const float* Whh  = (const float*)d_in[2];
    const float* bh   = (const float*)d_in[3];
    float* out        = (float*)d_out;

    conv_x_kernel<<<32768, 256>>>(X);
    conv_w_kernel<<<1024, 256>>>(Wxh);
    rnn_init_kernel<<<64, 256>>>();

    cudaFuncSetAttribute(gemm_bf16_kernel,
                         cudaFuncAttributeMaxDynamicSharedMemorySize,
                         GEMM_SMEM);
    dim3 gg(8, 256);
    gemm_bf16_kernel<<<gg, 256, GEMM_SMEM>>>(bh, out);

    cudaFuncSetAttribute(rnn_scan_kernel,
                         cudaFuncAttributeMaxDynamicSharedMemorySize,
                         SCAN_SMEM);
    int write_last = (out_size >= B_ * S_ * H_ + B_ * H_) ? 1 : 0;
    rnn_scan_kernel<<<128, 512, SCAN_SMEM>>>(Whh, out, write_last);
}

// round 14
// speedup vs baseline: 2.3463x; 1.0996x over previous
#include <cuda_runtime.h>
#include <cuda_bf16.h>
#include <math.h>

#define B_    32
#define S_    1024
#define IN_   1024
#define H_    1024

typedef unsigned long long ull;

// ---------------- device scratch (static, no dynamic allocation) ----------------
__device__ unsigned g_flags[4][32][64];    // one 256B line per (bg, cg)
__device__ __nv_bfloat16 g_Xhi[(size_t)B_ * S_ * IN_];   // [m][k]
__device__ __nv_bfloat16 g_Xlo[(size_t)B_ * S_ * IN_];
__device__ __nv_bfloat16 g_Whi[(size_t)IN_ * H_];        // [n][k] (W_xh transposed)
__device__ __nv_bfloat16 g_Wlo[(size_t)IN_ * H_];
__device__ __nv_bfloat16 g_Hbf[2][2][B_][H_];            // [phase][hi|lo][b][j]

// ---------------- generic helpers ----------------
__device__ __forceinline__ unsigned ld_acq(const unsigned* p) {
    unsigned v;
    asm volatile("ld.global.acquire.gpu.u32 %0, [%1];" : "=r"(v) : "l"(p));
    return v;
}
__device__ __forceinline__ void st_rel(unsigned* p, unsigned v) {
    asm volatile("st.global.release.gpu.u32 [%0], %1;" :: "l"(p), "r"(v));
}
__device__ __forceinline__ float tanh_fast(float x) {
    float a = x * 2.88539008177792681472f;   // 2*log2(e)
    float e;
    asm("ex2.approx.f32 %0, %1;" : "=f"(e) : "f"(a));
    float d = e + 1.0f;
    float r;
    asm("rcp.approx.f32 %0, %1;" : "=f"(r) : "f"(d));
    return fmaf(-2.0f, r, 1.0f);
}
__device__ __forceinline__ void cp_async16(void* smem_dst, const void* gsrc) {
    unsigned saddr = (unsigned)__cvta_generic_to_shared(smem_dst);
    asm volatile("cp.async.cg.shared.global [%0], [%1], 16;"
                 :: "r"(saddr), "l"(gsrc) : "memory");
}
__device__ __forceinline__ void cp_async_wait_all() {
    asm volatile("cp.async.wait_all;" ::: "memory");
}
__device__ __forceinline__ void cp_async_commit() {
    asm volatile("cp.async.commit_group;" ::: "memory");
}
__device__ __forceinline__ void cp_async_wait0() {
    asm volatile("cp.async.wait_group 0;" ::: "memory");
}

// ---------------- mma helpers (verified in R10 GEMM) ----------------
__device__ __forceinline__ void ldmx4(unsigned& r0, unsigned& r1, unsigned& r2,
                                      unsigned& r3, unsigned saddr) {
    asm volatile("ldmatrix.sync.aligned.m8n8.x4.shared.b16 {%0,%1,%2,%3}, [%4];"
                 : "=r"(r0), "=r"(r1), "=r"(r2), "=r"(r3) : "r"(saddr));
}
#define MMA_BF16(d, a, b0v, b1v)                                              \
    asm volatile(                                                             \
        "mma.sync.aligned.m16n8k16.row.col.f32.bf16.bf16.f32 "                \
        "{%0,%1,%2,%3},{%4,%5,%6,%7},{%8,%9},{%0,%1,%2,%3};"                  \
        : "+f"((d)[0]), "+f"((d)[1]), "+f"((d)[2]), "+f"((d)[3])              \
        : "r"((a)[0]), "r"((a)[1]), "r"((a)[2]), "r"((a)[3]),                 \
          "r"(b0v), "r"(b1v))

// ---------------- conversion kernels (split bf16 hi/lo) ----------------
__global__ void conv_x_kernel(const float* __restrict__ X) {
    size_t i = (size_t)blockIdx.x * blockDim.x + threadIdx.x;   // float4 index
    const float4* src = (const float4*)X;
    float4 v = src[i];
    __nv_bfloat16 hv[4], lv[4];
    float vv[4] = {v.x, v.y, v.z, v.w};
#pragma unroll
    for (int j = 0; j < 4; j++) {
        hv[j] = __float2bfloat16(vv[j]);
        lv[j] = __float2bfloat16(vv[j] - __bfloat162float(hv[j]));
    }
    *(uint2*)&g_Xhi[i * 4] = *(uint2*)hv;
    *(uint2*)&g_Xlo[i * 4] = *(uint2*)lv;
}
__global__ void conv_w_kernel(const float* __restrict__ W) {
    int idx = blockIdx.x * blockDim.x + threadIdx.x;
    int n  = idx & 1023;
    int k0 = (idx >> 10) * 4;
    __nv_bfloat16 hv[4], lv[4];
#pragma unroll
    for (int j = 0; j < 4; j++) {
        float w = W[(size_t)(k0 + j) * H_ + n];
        hv[j] = __float2bfloat16(w);
        lv[j] = __float2bfloat16(w - __bfloat162float(hv[j]));
    }
    *(uint2*)&g_Whi[(size_t)n * IN_ + k0] = *(uint2*)hv;
    *(uint2*)&g_Wlo[(size_t)n * IN_ + k0] = *(uint2*)lv;
}

// ---------------- init: zero flags ----------------
__global__ void rnn_init_kernel() {
    int idx = blockIdx.x * blockDim.x + threadIdx.x;
    int stride = gridDim.x * blockDim.x;
    unsigned* f = &g_flags[0][0][0];
    for (int i = idx; i < 4 * 32 * 64; i += stride) f[i] = 0u;
}

// ---------------- HMMA split-bf16 GEMM: Xp = X @ W_xh + b ----------------
// R13 structure; NOW 2 CTAs/SM (__launch_bounds__(256,2) -> <=128 regs) to
// hide cp.async fill latency + per-slab sync with co-resident work.
#define GKS       32
#define TROW      40
#define TILE_ELE  (128 * TROW)
#define BUF_ELE   (4 * TILE_ELE)
#define GEMM_SMEM (2 * BUF_ELE * 2)

extern __shared__ __nv_bfloat16 gbuf[];

__global__ void __launch_bounds__(256, 2) gemm_bf16_kernel(
    const float* __restrict__ bias, float* __restrict__ C)
{
    int tid  = threadIdx.x;
    int wid  = tid >> 5;
    int lane = tid & 31;
    int brow = blockIdx.y * 128;
    int bcol = blockIdx.x * 128;

    int wm = wid >> 2;
    int wn = wid & 3;

    int tIdx = tid >> 6;
    int frow = tid & 63;
    const __nv_bfloat16* gsrc =
        (tIdx == 0) ? g_Xhi + (size_t)brow * IN_ :
        (tIdx == 1) ? g_Xlo + (size_t)brow * IN_ :
        (tIdx == 2) ? g_Whi + (size_t)bcol * IN_ :
                      g_Wlo + (size_t)bcol * IN_;
    __nv_bfloat16* dtile0 = gbuf + tIdx * TILE_ELE;

    auto fill = [&](int s, int buf) {
        __nv_bfloat16* dt = dtile0 + buf * BUF_ELE;
#pragma unroll
        for (int c = 0; c < 8; c++) {
            int row = frow + (c >> 2) * 64;
            int q   = c & 3;
            cp_async16(dt + row * TROW + q * 8,
                       gsrc + (size_t)row * IN_ + s * GKS + q * 8);
        }
    };

    int lrA = (lane & 7) + ((lane >> 3) & 1) * 8;
    int lkA = ((lane >> 4) & 1) * 8;
    int lnB = (lane & 7) + ((lane >> 4) & 1) * 8;
    int lkB = ((lane >> 3) & 1) * 8;

    unsigned sbase = (unsigned)__cvta_generic_to_shared(gbuf);
    unsigned offAhi = 0, offAlo = TILE_ELE * 2;
    unsigned offBhi = 2 * TILE_ELE * 2, offBlo = 3 * TILE_ELE * 2;

    float acc[4][4][4];
#pragma unroll
    for (int mi = 0; mi < 4; mi++)
#pragma unroll
        for (int ni = 0; ni < 4; ni++)
#pragma unroll
            for (int e = 0; e < 4; e++) acc[mi][ni][e] = 0.0f;

    fill(0, 0);
    cp_async_commit();

    for (int s = 0; s < IN_ / GKS; s++) {
        int buf = s & 1;
        cp_async_wait0();
        __syncthreads();
        if (s < IN_ / GKS - 1) {
            fill(s + 1, buf ^ 1);
            cp_async_commit();
        }
        unsigned bb = sbase + buf * (BUF_ELE * 2);

#pragma unroll
        for (int kk = 0; kk < GKS; kk += 16) {
            unsigned ah[4][4], al[4][4];
#pragma unroll
            for (int mi = 0; mi < 4; mi++) {
                unsigned ro = (unsigned)((wm * 64 + mi * 16 + lrA) * TROW + kk + lkA) * 2;
                ldmx4(ah[mi][0], ah[mi][1], ah[mi][2], ah[mi][3], bb + offAhi + ro);
                ldmx4(al[mi][0], al[mi][1], al[mi][2], al[mi][3], bb + offAlo + ro);
            }
            unsigned bh[2][4], bl[2][4];
#pragma unroll
            for (int np = 0; np < 2; np++) {
                unsigned ro = (unsigned)((wn * 32 + np * 16 + lnB) * TROW + kk + lkB) * 2;
                ldmx4(bh[np][0], bh[np][1], bh[np][2], bh[np][3], bb + offBhi + ro);
                ldmx4(bl[np][0], bl[np][1], bl[np][2], bl[np][3], bb + offBlo + ro);
            }
#pragma unroll
            for (int mi = 0; mi < 4; mi++)
#pragma unroll
                for (int ni = 0; ni < 4; ni++) {
                    int pr = ni >> 1, wh = (ni & 1) * 2;
                    MMA_BF16(acc[mi][ni], ah[mi], bh[pr][wh], bh[pr][wh + 1]);
                    MMA_BF16(acc[mi][ni], ah[mi], bl[pr][wh], bl[pr][wh + 1]);
                    MMA_BF16(acc[mi][ni], al[mi], bh[pr][wh], bh[pr][wh + 1]);
                }
        }
    }

    int gr = lane >> 2;
    int gc = (lane & 3) * 2;
#pragma unroll
    for (int ni = 0; ni < 4; ni++) {
        int col = bcol + wn * 32 + ni * 8 + gc;
        float2 bv = *(const float2*)&bias[col];
#pragma unroll
        for (int mi = 0; mi < 4; mi++) {
            int row0 = brow + wm * 64 + mi * 16 + gr;
            float2 o0 = make_float2(acc[mi][ni][0] + bv.x, acc[mi][ni][1] + bv.y);
            float2 o1 = make_float2(acc[mi][ni][2] + bv.x, acc[mi][ni][3] + bv.y);
            *(float2*)&C[(size_t)row0 * H_ + col]       = o0;
            *(float2*)&C[(size_t)(row0 + 8) * H_ + col] = o1;
        }
    }
}

// ---------------- HMMA recurrent scan, fine-grained dataflow (R13 champion) ----------------
#define SAST      1032                       // bf16 per row (pad 8)
#define SASTB     (SAST * 2)                 // 2064 bytes
#define WJ_HI     0                          // [32][SAST] preload (transient)
#define WJ_LO     (32 * SASTB)
#define HB_HI     0                          // [8][SAST] staging
#define HB_LO     (8 * SASTB)
#define SRED_OFF  (16 * SASTB)               // 33024
#define SRED_WST  288                        // floats/warp: 32 j * stride 9
#define SCAN_SMEM (64 * SASTB)               // 132096 (preload dominates)

extern __shared__ char scan_smem_c[];

__global__ void __launch_bounds__(512, 1) rnn_scan_kernel(
    const float* __restrict__ Whh,
    float* __restrict__ out,
    int write_last)
{
    char* smem = scan_smem_c;
    unsigned sbase = (unsigned)__cvta_generic_to_shared(smem);
    float* red = (float*)(smem + SRED_OFF);

    int tid  = threadIdx.x;
    int wid  = tid >> 5;
    int lane = tid & 31;
    int cta  = blockIdx.x;
    int bg   = cta >> 5;      // 0..3 -> batches bg*8..+7
    int cg   = cta & 31;      // cols cg*32..+31
    int b0   = bg * 8;
    int j0   = cg * 32;

    int lrA = (lane & 7) + ((lane >> 3) & 1) * 8;
    int lkA = ((lane >> 4) & 1) * 8;

    // ---- preload W_hh slice -> SMEM split planes [j 0..31][k 0..1023] ----
    {
        int j = tid & 31;
        for (int k = tid >> 5; k < H_; k += 16) {
            float w = Whh[(size_t)k * H_ + j0 + j];
            __nv_bfloat16 h = __float2bfloat16(w);
            __nv_bfloat16 l = __float2bfloat16(w - __bfloat162float(h));
            *(__nv_bfloat16*)(smem + WJ_HI + j * SASTB + k * 2) = h;
            *(__nv_bfloat16*)(smem + WJ_LO + j * SASTB + k * 2) = l;
        }
    }
    __syncthreads();

    // ---- load W A-fragments into registers (64 regs) ----
    int warpk = wid * 64;
    unsigned wah[2][4][4], wal[2][4][4];
#pragma unroll
    for (int mi = 0; mi < 2; mi++)
#pragma unroll
        for (int ks = 0; ks < 4; ks++) {
            unsigned ro = (unsigned)((mi * 16 + lrA) * SASTB +
                                     (warpk + ks * 16 + lkA) * 2);
            ldmx4(wah[mi][ks][0], wah[mi][ks][1], wah[mi][ks][2], wah[mi][ks][3],
                  sbase + WJ_HI + ro);
            ldmx4(wal[mi][ks][0], wal[mi][ks][1], wal[mi][ks][2], wal[mi][ks][3],
                  sbase + WJ_LO + ro);
        }
    __syncthreads();   // W SMEM region now reusable for H staging + red

    // ---- H b-frag ldmatrix lane address ----
    int hrow = lane & 7;
    int hcol = (lane >> 3) * 8;

    // ---- consumer mapping: thread (tid<256) owns output (j=lane, b=tid>>5) ----
    int ob = tid >> 5;
    int oj = lane;
    size_t out_base = ((size_t)(b0 + ob) * S_) * H_ + j0 + oj;

    unsigned* relp = &g_flags[bg][cg][0];
    // warp w polls its 2 producers: lanes alternate the two flag lines
    const unsigned* wpoll = &g_flags[bg][2 * wid + (lane & 1)][0];

    // per-lane staging map: 4 chunks, col16 = lane&7 fixed, plane/row vary
    int s_col16 = 8 * wid + (lane & 7);      // 16B-chunk column in full row
    float v = 0.0f;

    // ---- step 0: H1 = tanh(Xp0), no matmul ----
    {
        if (tid < 256) {
            float xp = __ldcg(&out[out_base]);
            v = tanh_fast(xp);
            __nv_bfloat16 h = __float2bfloat16(v);
            __nv_bfloat16 l = __float2bfloat16(v - __bfloat162float(h));
            g_Hbf[1][0][b0 + ob][j0 + oj] = h;
            g_Hbf[1][1][b0 + ob][j0 + oj] = l;
            out[out_base] = v;
        }
        __syncthreads();
        if (tid == 0) st_rel(relp, 1u);
    }

    for (int t = 1; t < S_; t++) {
        int ph = t & 1;
        float xp = 0.0f;
        if (tid < 256) xp = __ldcg(&out[out_base + (size_t)t * H_]);

        // ---- per-warp poll of the warp's 2 producers ----
        while (ld_acq(wpoll) < (unsigned)t) { }
        __syncwarp();

        // ---- stage warp's own k-slice: 8 rows x 64 cols x 2 planes = 2KB ----
        {
#pragma unroll
            for (int q = 0; q < 4; q++) {
                int c   = lane + q * 32;        // 0..127
                int pl  = c >> 6;               // 0 hi, 1 lo
                int row = (c >> 3) & 7;         // 0..7
                cp_async16(smem + (pl ? HB_LO : HB_HI) + row * SASTB + s_col16 * 16,
                           &g_Hbf[ph][pl][b0 + row][s_col16 * 8]);
            }
            cp_async_wait_all();
            __syncwarp();
        }

        // ---- H b-frags: 2 ldmx4 per plane (k-slice 64) ----
        unsigned hb[2][4], lb[2][4];
#pragma unroll
        for (int c32 = 0; c32 < 2; c32++) {
            unsigned ro = (unsigned)(hrow * SASTB + (warpk + c32 * 32 + hcol) * 2);
            ldmx4(hb[c32][0], hb[c32][1], hb[c32][2], hb[c32][3],
                  sbase + HB_HI + ro);
            ldmx4(lb[c32][0], lb[c32][1], lb[c32][2], lb[c32][3],
                  sbase + HB_LO + ro);
        }

        // ---- 24 HMMA: D[j, b] partials over this warp's k-slice ----
        float acc[2][4];
#pragma unroll
        for (int mi = 0; mi < 2; mi++)
#pragma unroll
            for (int e = 0; e < 4; e++) acc[mi][e] = 0.0f;

#pragma unroll
        for (int ks = 0; ks < 4; ks++) {
            int c32 = ks >> 1, sel = (ks & 1) * 2;
            unsigned b0h = hb[c32][sel], b1h = hb[c32][sel + 1];
            unsigned b0l = lb[c32][sel], b1l = lb[c32][sel + 1];
#pragma unroll
            for (int mi = 0; mi < 2; mi++) {
                MMA_BF16(acc[mi], wah[mi][ks], b0h, b1h);   // Whi x Hhi
                MMA_BF16(acc[mi], wah[mi][ks], b0l, b1l);   // Whi x Hlo
                MMA_BF16(acc[mi], wal[mi][ks], b0h, b1h);   // Wlo x Hhi
            }
        }

        // ---- partial store: red[wid][j*9 + b] ----
        {
            int gr = lane >> 2;
            int gc = (lane & 3) * 2;
            float* rw = red + wid * SRED_WST;
#pragma unroll
            for (int mi = 0; mi < 2; mi++)
#pragma unroll
                for (int e = 0; e < 4; e++) {
                    int j = mi * 16 + gr + (e >> 1) * 8;
                    int b = gc + (e & 1);
                    rw[j * 9 + b] = acc[mi][e];
                }
        }
        __syncthreads();

        // ---- combine 16 k-slices, tanh, publish split planes ----
        if (tid < 256) {
            float s = 0.0f;
            int rbase = oj * 9 + ob;
#pragma unroll
            for (int w = 0; w < 16; w++)
                s += red[w * SRED_WST + rbase];
            v = tanh_fast(s + xp);
            int php = (t + 1) & 1;
            __nv_bfloat16 h = __float2bfloat16(v);
            __nv_bfloat16 l = __float2bfloat16(v - __bfloat162float(h));
            g_Hbf[php][0][b0 + ob][j0 + oj] = h;
            g_Hbf[php][1][b0 + ob][j0 + oj] = l;
        }
        __syncthreads();
        if (tid == 0) st_rel(relp, (unsigned)(t + 1));

        // out store after release: off the critical path
        if (tid < 256) out[out_base + (size_t)t * H_] = v;
    }

    if (write_last && tid < 256)
        out[(size_t)B_ * S_ * H_ + (size_t)(b0 + ob) * H_ + j0 + oj] = v;
}

// ---------------- launch ----------------
extern "C" void kernel_launch(void* const* d_in, const int* in_sizes, int n_in,
                              void* d_out, int out_size) {
    const float* X    = (const float*)d_in[0];
    const float* Wxh  = (const float*)d_in[1];
    const float* Whh  = (const float*)d_in[2];
    const float* bh   = (const float*)d_in[3];
    float* out        = (float*)d_out;

    conv_x_kernel<<<32768, 256>>>(X);
    conv_w_kernel<<<1024, 256>>>(Wxh);
    rnn_init_kernel<<<64, 256>>>();

    cudaFuncSetAttribute(gemm_bf16_kernel,
                         cudaFuncAttributeMaxDynamicSharedMemorySize,
                         GEMM_SMEM);
    dim3 gg(8, 256);
    gemm_bf16_kernel<<<gg, 256, GEMM_SMEM>>>(bh, out);

    cudaFuncSetAttribute(rnn_scan_kernel,
                         cudaFuncAttributeMaxDynamicSharedMemorySize,
                         SCAN_SMEM);
    int write_last = (out_size >= B_ * S_ * H_ + B_ * H_) ? 1 : 0;
    rnn_scan_kernel<<<128, 512, SCAN_SMEM>>>(Whh, out, write_last);
}